// round 16
// baseline (speedup 1.0000x reference)
#include <cuda_runtime.h>
#include <cuda_bf16.h>
#include <math.h>
#include <stdint.h>

// Problem dims (fixed by setup_inputs)
#define B_   256
#define D_   256
#define D1   1024
#define D2   512
#define D3   256
#define NDIST (D1 + D2 + D3)   // 1792
#define KSEL 10

// ---------------- scratch (device globals; no cudaMalloc allowed) ----------
__device__ float g_z1[B_ * D1];
__device__ float g_h1[B_ * D1];
__device__ float g_z2[B_ * D2];
__device__ float g_h2[B_ * D2];
__device__ float g_z3[B_ * D3];
__device__ __nv_bfloat16 g_W2T[(D1 + 1) * D2];            // [1025][512], row 1024 = 0
__device__ __nv_bfloat16 g_W3T[(D2 + 1) * D3];            // [513][256],  row 512  = 0
__device__ __nv_bfloat16 g_W1b[D1 * D_];                  // [1024][256]
__device__ __nv_bfloat16 g_V2[(size_t)B_ * D2 * D_];      // [B][512][256] row-major
__device__ int g_kidx1[B_ * (D1 + 32)];
__device__ int g_cnt1[B_];
__device__ int g_kidx2[B_ * (D2 + 32)];
__device__ int g_cnt2[B_];
__device__ float g_invn1[D1];
__device__ float g_sqp2[2 * B_ * D2];                     // [ntile][b][m]
__device__ float g_sqp3[2 * B_ * D3];
__device__ float g_partial[B_];

// ---------------- PTX helpers ------------------------------------------------
__device__ __forceinline__ uint32_t smem_u32(const void* p) {
    uint32_t a;
    asm("{ .reg .u64 t; cvta.to.shared.u64 t, %1; cvt.u32.u64 %0, t; }"
        : "=r"(a) : "l"(p));
    return a;
}
__device__ __forceinline__ void cpasync16(uint32_t dst, const void* src) {
    asm volatile("cp.async.cg.shared.global [%0], [%1], 16;"
                 :: "r"(dst), "l"(src) : "memory");
}
__device__ __forceinline__ void ldm4t(uint32_t* r, uint32_t addr) {
    asm volatile("ldmatrix.sync.aligned.m8n8.x4.trans.shared.b16 {%0,%1,%2,%3}, [%4];"
                 : "=r"(r[0]), "=r"(r[1]), "=r"(r[2]), "=r"(r[3]) : "r"(addr));
}
__device__ __forceinline__ void mma16816(float* c, const uint32_t* a,
                                         uint32_t b0, uint32_t b1) {
    asm volatile(
        "mma.sync.aligned.m16n8k16.row.col.f32.bf16.bf16.f32 "
        "{%0,%1,%2,%3}, {%4,%5,%6,%7}, {%8,%9}, {%0,%1,%2,%3};"
        : "+f"(c[0]), "+f"(c[1]), "+f"(c[2]), "+f"(c[3])
        : "r"(a[0]), "r"(a[1]), "r"(a[2]), "r"(a[3]), "r"(b0), "r"(b1));
}

// ---------------- forward-pass GEMM body (device fn, callable from fused) ---
// BM=32, BN=64, BK=32; 256 threads; 2x4 per-thread microtile. (R13 version)
__device__ void zgemm_body(
    const float* __restrict__ X, const float* __restrict__ W,
    const float* __restrict__ bias, int M, int N, int K,
    float* __restrict__ Z, float* __restrict__ H,
    int bx, int by, float* Xs /*[32][34]*/, float* Ws /*[32][68]*/)
{
    int m0 = by * 32, n0 = bx * 64;
    int tid = threadIdx.x;
    int tx = tid & 15, ty = tid >> 4;
    int lrow = tid >> 3, lk = (tid & 7) * 4;

    float acc[2][4];
#pragma unroll
    for (int i = 0; i < 2; i++)
#pragma unroll
        for (int j = 0; j < 4; j++) acc[i][j] = 0.f;

    for (int k0 = 0; k0 < K; k0 += 32) {
        float4 xa = *(const float4*)(X + (size_t)(m0 + lrow) * K + k0 + lk);
        float4 w0 = *(const float4*)(W + (size_t)(n0 + lrow) * K + k0 + lk);
        float4 w1 = *(const float4*)(W + (size_t)(n0 + lrow + 32) * K + k0 + lk);
        __syncthreads();
        Xs[(lk + 0) * 34 + lrow] = xa.x; Xs[(lk + 1) * 34 + lrow] = xa.y;
        Xs[(lk + 2) * 34 + lrow] = xa.z; Xs[(lk + 3) * 34 + lrow] = xa.w;
        Ws[(lk + 0) * 68 + lrow] = w0.x; Ws[(lk + 1) * 68 + lrow] = w0.y;
        Ws[(lk + 2) * 68 + lrow] = w0.z; Ws[(lk + 3) * 68 + lrow] = w0.w;
        Ws[(lk + 0) * 68 + lrow + 32] = w1.x; Ws[(lk + 1) * 68 + lrow + 32] = w1.y;
        Ws[(lk + 2) * 68 + lrow + 32] = w1.z; Ws[(lk + 3) * 68 + lrow + 32] = w1.w;
        __syncthreads();
#pragma unroll
        for (int k = 0; k < 32; k++) {
            float a0 = Xs[k * 34 + ty * 2], a1 = Xs[k * 34 + ty * 2 + 1];
            float4 wv = *(float4*)&Ws[k * 68 + tx * 4];
            acc[0][0] += a0 * wv.x; acc[0][1] += a0 * wv.y;
            acc[0][2] += a0 * wv.z; acc[0][3] += a0 * wv.w;
            acc[1][0] += a1 * wv.x; acc[1][1] += a1 * wv.y;
            acc[1][2] += a1 * wv.z; acc[1][3] += a1 * wv.w;
        }
    }

#pragma unroll
    for (int i = 0; i < 2; i++) {
        int m = m0 + ty * 2 + i;
#pragma unroll
        for (int j = 0; j < 4; j++) {
            int n = n0 + tx * 4 + j;
            float zv = acc[i][j] + bias[n];
            size_t o = (size_t)m * N + n;
            Z[o] = zv;
            if (H) H[o] = zv > 0.f ? zv : 0.f;
        }
    }
}

// ---------------- deterministic per-batch active-k compaction (device fn) --
template <int KN>
__device__ __forceinline__ void compact_body(
    const float* __restrict__ z, int* __restrict__ kidx, int* __restrict__ cnt,
    int b, int t, int* sh /*[256]*/)
{
    const int E = KN / 256;
    const int kpitch = KN + 32;
    int flag[E];
    int c = 0;
#pragma unroll
    for (int e = 0; e < E; e++) {
        flag[e] = (z[(size_t)b * KN + t * E + e] > 0.f) ? 1 : 0;
        c += flag[e];
    }
    sh[t] = c;
    __syncthreads();
    for (int s = 1; s < 256; s <<= 1) {
        int x = (t >= s) ? sh[t - s] : 0;
        __syncthreads();
        sh[t] += x;
        __syncthreads();
    }
    int pos = sh[t] - c;
#pragma unroll
    for (int e = 0; e < E; e++)
        if (flag[e]) kidx[(size_t)b * kpitch + pos++] = t * E + e;
    int total = sh[255];
    int padded = (total + 31) & ~31;
    int ip = total + t;
    if (ip < padded) kidx[(size_t)b * kpitch + ip] = KN;  // -> zero row of A^T
    if (t == 0) cnt[b] = total;
}

// fused #1: zgemm1 (128 blks) + W2T tile-transpose (513) + W1 cast (1024)
//           + W1 row inv-norms (128).  W-only work overlaps zgemm1.
// grid = 128 + 513 + 1024 + 128 = 1793
__global__ __launch_bounds__(256) void fused_prep1(
    const float* __restrict__ x, const float* __restrict__ W1,
    const float* __restrict__ b1, const float* __restrict__ W2,
    float* __restrict__ z1, float* __restrict__ h1)
{
    __shared__ __align__(16) float smem[32 * 68 + 32 * 34];
    int blk = blockIdx.x, t = threadIdx.x;
    if (blk < 128) {
        // z1 = x @ W1^T + b1   (grid 16x8: bx = blk&15, by = blk>>4)
        zgemm_body(x, W1, b1, B_, D1, D_, z1, h1,
                   blk & 15, blk >> 4, smem, smem + 32 * 34);
    } else if (blk < 128 + 512) {
        // transpose one 32(m) x 32(k) tile of W2 [512][1024] -> W2T [1025][512]
        float* tile = smem;   // [32][33]
        int bi = blk - 128;
        int k0 = (bi & 31) * 32, m0 = (bi >> 5) * 32;
        int r = t >> 3, c4 = (t & 7) * 4;
        float4 v = *(const float4*)(W2 + (size_t)(m0 + r) * D1 + k0 + c4);
        tile[r * 33 + c4 + 0] = v.x; tile[r * 33 + c4 + 1] = v.y;
        tile[r * 33 + c4 + 2] = v.z; tile[r * 33 + c4 + 3] = v.w;
        __syncthreads();
        __nv_bfloat16 o[4];
#pragma unroll
        for (int i = 0; i < 4; i++) o[i] = __float2bfloat16(tile[(c4 + i) * 33 + r]);
        *(uint2*)&g_W2T[(size_t)(k0 + r) * D2 + m0 + c4] = *(uint2*)o;
    } else if (blk < 128 + 512 + 1) {
        if (t < 128)
            ((uint2*)&g_W2T[(size_t)D1 * D2])[t] = make_uint2(0u, 0u);
    } else if (blk < 128 + 513 + 1024) {
        int i = (blk - 128 - 513) * 256 + t;
        g_W1b[i] = __float2bfloat16(W1[i]);
    } else {
        int warp = (blk - 128 - 513 - 1024) * 8 + (t >> 5);
        int lane = t & 31;
        const float4* vp = (const float4*)(W1 + (size_t)warp * D_);
        float4 v0 = vp[lane * 2], v1 = vp[lane * 2 + 1];
        float s = v0.x * v0.x + v0.y * v0.y + v0.z * v0.z + v0.w * v0.w
                + v1.x * v1.x + v1.y * v1.y + v1.z * v1.z + v1.w * v1.w;
#pragma unroll
        for (int o = 16; o; o >>= 1) s += __shfl_xor_sync(0xffffffffu, s, o);
        if (lane == 0) g_invn1[warp] = rsqrtf(s);
    }
}

// fused #2: zgemm2 (64 blks) + compact(z1) (256).  grid = 320
__global__ __launch_bounds__(256) void fused_prep2(
    const float* __restrict__ h1, const float* __restrict__ W2,
    const float* __restrict__ b2, const float* __restrict__ z1,
    float* __restrict__ z2, float* __restrict__ h2)
{
    __shared__ __align__(16) float smem[32 * 68 + 32 * 34];
    int blk = blockIdx.x, t = threadIdx.x;
    if (blk < 64) {
        // z2 = h1 @ W2^T + b2   (grid 8x8: bx = blk&7, by = blk>>3)
        zgemm_body(h1, W2, b2, B_, D2, D1, z2, h2,
                   blk & 7, blk >> 3, smem, smem + 32 * 34);
    } else {
        compact_body<D1>(z1, g_kidx1, g_cnt1, blk - 64, t, (int*)smem);
    }
}

// fused #3: zgemm3 (32 blks) + compact(z2) + W3T cast.  grid = 32 + 256 + 513
__global__ __launch_bounds__(256) void fused_prep3(
    const float* __restrict__ h2, const float* __restrict__ W3,
    const float* __restrict__ b3,
    const float* __restrict__ z2, float* __restrict__ z3)
{
    __shared__ __align__(16) float smem[32 * 68 + 32 * 34];
    int blk = blockIdx.x, t = threadIdx.x;
    if (blk < 32) {
        // z3 = h2 @ W3^T + b3   (grid 4x8: bx = blk&3, by = blk>>2)
        zgemm_body(h2, W3, b3, B_, D3, D2, z3, (float*)0,
                   blk & 3, blk >> 2, smem, smem + 32 * 34);
    } else if (blk < 32 + 256) {
        compact_body<D2>(z2, g_kidx2, g_cnt2, blk - 32, t, (int*)smem);
    } else {
        int i = (blk - 32 - 256) * 256 + t;
        if (i < (D2 + 1) * D3) {
            int k = i >> 8, m = i & 255;
            g_W3T[i] = (k < D2) ? __float2bfloat16(W3[(size_t)m * D2 + k])
                                : __float2bfloat16(0.f);
        }
    }
}

// ---------------- HMMA k-compacted batched GEMM (128x128 tile) --------------
// grid (Mtot/128, 2 ntiles, B_); 256 threads; 2 CTAs/SM.
// 4-stage cp.async ring, depth-3 prefetch, B-fragment double buffering.
// (R10/R13 configuration — measured 142.8us on layer 2. DO NOT TOUCH.)
#define APITCH 272               // 32k x 128m bf16 rows padded to 272B
#define BPITCH 272               // 32k x 128n bf16 rows padded to 272B
#define ASTG   (32 * APITCH)     // 8704
#define BSTG   (32 * BPITCH)     // 8704
#define STGC   (ASTG + BSTG)     // 17408
#define NSTG   4
#define SQOFF  (NSTG * STGC)     // 69632
#define SMEMC  (SQOFF + 1024)

__global__ __launch_bounds__(256, 2) void hmma_comp(
    const __nv_bfloat16* __restrict__ AT, const __nv_bfloat16* __restrict__ Bk,
    size_t bstrideB, int bclamp,
    const int* __restrict__ kidx, const int* __restrict__ cnt, int kpitch,
    int Mtot, float* __restrict__ sqout,
    __nv_bfloat16* __restrict__ Vout)
{
    extern __shared__ __align__(16) char smem[];
    const uint32_t sb = smem_u32(smem);
    const int tid = threadIdx.x, wid = tid >> 5, lane = tid & 31;
    const int warpM = wid >> 1, warpN = wid & 1;   // 4 x 2, warp tile 32x64
    const int m0 = blockIdx.x * 128, n0 = blockIdx.y * 128;
    const int b = blockIdx.z;

    const __nv_bfloat16* Bb = Bk + (size_t)b * bstrideB;
    const int* kp = kidx + (size_t)b * kpitch;
    const int nch = (cnt[b] + 31) >> 5;

    float c[2][8][4];
#pragma unroll
    for (int i = 0; i < 2; i++)
#pragma unroll
        for (int j = 0; j < 8; j++)
#pragma unroll
            for (int r = 0; r < 4; r++) c[i][j][r] = 0.f;

    const int gr = tid >> 3;          // 0..31: gathered row within chunk
    const int sg = tid & 7;           // 8 threads per row; 2x16B segs each

    auto load_stage = [&](int s, int cc) {
        if (cc < nch) {
            uint32_t st = sb + s * STGC;
            int k = __ldg(kp + cc * 32 + gr);
            const __nv_bfloat16* asrc = AT + (size_t)k * Mtot + m0 + sg * 16;
            cpasync16(st + gr * APITCH + sg * 32, asrc);
            cpasync16(st + gr * APITCH + sg * 32 + 16, asrc + 8);
            int kb = min(k, bclamp);
            const __nv_bfloat16* bsrc = Bb + (size_t)kb * 256 + n0 + sg * 16;
            cpasync16(st + ASTG + gr * BPITCH + sg * 32, bsrc);
            cpasync16(st + ASTG + gr * BPITCH + sg * 32 + 16, bsrc + 8);
        }
        asm volatile("cp.async.commit_group;" ::: "memory");
    };

    if (nch > 0) {
        load_stage(0, 0);
        load_stage(1, 1);
        load_stage(2, 2);

        const int kr = (lane & 7) + ((lane >> 4) << 3);  // k-row within 16-blk
        const int ch8 = ((lane >> 3) & 1) << 3;          // +8 col for odd octet

        for (int cidx = 0; cidx < nch; cidx++) {
            int cur = cidx & (NSTG - 1);
            asm volatile("cp.async.wait_group 2;" ::: "memory");
            __syncthreads();
            load_stage((cidx + 3) & (NSTG - 1), cidx + 3);

            uint32_t aBase = sb + cur * STGC;
            uint32_t bBase = aBase + ASTG;
#pragma unroll
            for (int ks = 0; ks < 2; ks++) {
                uint32_t arow = aBase + (uint32_t)(ks * 16 + kr) * APITCH;
                uint32_t brow = bBase + (uint32_t)(ks * 16 + kr) * BPITCH;
                uint32_t a0[4], a1[4], bcur[4], bnxt[4];
                ldm4t(a0, arow + (uint32_t)(warpM * 32 + ch8) * 2);
                ldm4t(a1, arow + (uint32_t)(warpM * 32 + 16 + ch8) * 2);
                ldm4t(bcur, brow + (uint32_t)(warpN * 64 + ch8) * 2);
#pragma unroll
                for (int gi = 0; gi < 4; gi++) {
                    if (gi < 3)
                        ldm4t(bnxt, brow + (uint32_t)(warpN * 64 + (gi + 1) * 16 + ch8) * 2);
                    mma16816(c[0][gi * 2],     a0, bcur[0], bcur[2]);
                    mma16816(c[0][gi * 2 + 1], a0, bcur[1], bcur[3]);
                    mma16816(c[1][gi * 2],     a1, bcur[0], bcur[2]);
                    mma16816(c[1][gi * 2 + 1], a1, bcur[1], bcur[3]);
                    bcur[0] = bnxt[0]; bcur[1] = bnxt[1];
                    bcur[2] = bnxt[2]; bcur[3] = bnxt[3];
                }
            }
        }
        asm volatile("cp.async.wait_group 0;" ::: "memory");
        __syncthreads();
    }

    // ---- per-row partial sum-of-squares (deterministic order) ----
    float* sqsm = (float*)(smem + SQOFF);   // [2 warpN][128 rows]
    {
        float rs[2][2] = {{0.f, 0.f}, {0.f, 0.f}};
#pragma unroll
        for (int mi = 0; mi < 2; mi++)
#pragma unroll
            for (int nj = 0; nj < 8; nj++)
#pragma unroll
                for (int r = 0; r < 4; r++) {
                    float v = c[mi][nj][r];
                    rs[mi][r >> 1] += v * v;
                }
#pragma unroll
        for (int mi = 0; mi < 2; mi++)
#pragma unroll
            for (int h = 0; h < 2; h++) {
                float v = rs[mi][h];
                v += __shfl_xor_sync(0xffffffffu, v, 1);
                v += __shfl_xor_sync(0xffffffffu, v, 2);
                rs[mi][h] = v;
            }
        if ((lane & 3) == 0) {
#pragma unroll
            for (int mi = 0; mi < 2; mi++)
#pragma unroll
                for (int h = 0; h < 2; h++)
                    sqsm[warpN * 128 + warpM * 32 + mi * 16 + h * 8 + (lane >> 2)]
                        = rs[mi][h];
        }
    }
    __syncthreads();
    if (tid < 128) {
        float s = sqsm[tid] + sqsm[128 + tid];
        sqout[((size_t)blockIdx.y * B_ + b) * Mtot + m0 + tid] = s;
    }

    // ---- V writeback (row-major C, layer 2 only) ----
    if (Vout) {
        __nv_bfloat16* Vb = Vout + (size_t)b * Mtot * 256;
#pragma unroll
        for (int mi = 0; mi < 2; mi++)
#pragma unroll
            for (int nj = 0; nj < 8; nj++)
#pragma unroll
                for (int rp = 0; rp < 2; rp++) {
                    int row = m0 + warpM * 32 + mi * 16 + rp * 8 + (lane >> 2);
                    int col = n0 + warpN * 64 + nj * 8 + (lane & 3) * 2;
                    __nv_bfloat162 p;
                    p.x = __float2bfloat16(c[mi][nj][rp * 2]);
                    p.y = __float2bfloat16(c[mi][nj][rp * 2 + 1]);
                    *(__nv_bfloat162*)(Vb + (size_t)row * 256 + col) = p;
                }
    }
}

// ---------------- per-batch smallest-k sum (warp-shuffle argmin) ------------
__global__ void topk_kernel(const float* __restrict__ z1,
                            const float* __restrict__ z2,
                            const float* __restrict__ z3)
{
    __shared__ float s[NDIST];
    __shared__ float wv[8];
    __shared__ int   wi[8];
    int b = blockIdx.x, t = threadIdx.x;
    int wid = t >> 5, lane = t & 31;

    for (int i = t; i < D1; i += 256)
        s[i] = fabsf(z1[(size_t)b * D1 + i]) * g_invn1[i];
    for (int i = t; i < D2; i += 256) {
        float sq = g_sqp2[(size_t)b * D2 + i] + g_sqp2[(size_t)(B_ + b) * D2 + i];
        s[D1 + i] = fabsf(z2[(size_t)b * D2 + i]) * rsqrtf(sq);
    }
    if (t < D3) {
        float sq = g_sqp3[(size_t)b * D3 + t] + g_sqp3[(size_t)(B_ + b) * D3 + t];
        s[D1 + D2 + t] = fabsf(z3[(size_t)b * D3 + t]) * rsqrtf(sq);
    }
    __syncthreads();

    float tot = 0.f;
    for (int it = 0; it < KSEL; it++) {
        float best = 3.402823466e38f; int bi = NDIST;
        for (int i = t; i < NDIST; i += 256) {
            float v = s[i];
            if (v < best) { best = v; bi = i; }
        }
#pragma unroll
        for (int off = 16; off; off >>= 1) {
            float ov = __shfl_down_sync(0xffffffffu, best, off);
            int   oi = __shfl_down_sync(0xffffffffu, bi,   off);
            if (ov < best || (ov == best && oi < bi)) { best = ov; bi = oi; }
        }
        if (lane == 0) { wv[wid] = best; wi[wid] = bi; }
        __syncthreads();
        if (wid == 0) {
            float fb = (lane < 8) ? wv[lane] : 3.402823466e38f;
            int   fi = (lane < 8) ? wi[lane] : NDIST;
#pragma unroll
            for (int off = 4; off; off >>= 1) {
                float ov = __shfl_down_sync(0xffffffffu, fb, off);
                int   oi = __shfl_down_sync(0xffffffffu, fi, off);
                if (ov < fb || (ov == fb && oi < fi)) { fb = ov; fi = oi; }
            }
            if (lane == 0) { tot += fb; s[fi] = 3.402823466e38f; }
        }
        __syncthreads();
    }
    if (t == 0) g_partial[b] = tot;
}

__global__ void final_reduce(float* __restrict__ out)
{
    __shared__ float sh[256];
    int t = threadIdx.x;
    sh[t] = g_partial[t];
    __syncthreads();
    for (int st = 128; st > 0; st >>= 1) {
        if (t < st) sh[t] += sh[t + st];
        __syncthreads();
    }
    if (t == 0) out[0] = sh[0];
}

// ---------------- launch -----------------------------------------------------
extern "C" void kernel_launch(void* const* d_in, const int* in_sizes, int n_in,
                              void* d_out, int out_size)
{
    const float* x  = (const float*)d_in[0];
    const float* W1 = (const float*)d_in[1];
    const float* b1 = (const float*)d_in[2];
    const float* W2 = (const float*)d_in[3];
    const float* b2 = (const float*)d_in[4];
    const float* W3 = (const float*)d_in[5];
    const float* b3 = (const float*)d_in[6];
    float* out = (float*)d_out;

    float *z1p, *h1p, *z2p, *h2p, *z3p, *sq2p, *sq3p;
    __nv_bfloat16 *w2t, *w3t, *w1b, *v2;
    int *ki1, *ci1, *ki2, *ci2;
    cudaGetSymbolAddress((void**)&z1p, g_z1);
    cudaGetSymbolAddress((void**)&h1p, g_h1);
    cudaGetSymbolAddress((void**)&z2p, g_z2);
    cudaGetSymbolAddress((void**)&h2p, g_h2);
    cudaGetSymbolAddress((void**)&z3p, g_z3);
    cudaGetSymbolAddress((void**)&sq2p, g_sqp2);
    cudaGetSymbolAddress((void**)&sq3p, g_sqp3);
    cudaGetSymbolAddress((void**)&w2t, g_W2T);
    cudaGetSymbolAddress((void**)&w3t, g_W3T);
    cudaGetSymbolAddress((void**)&w1b, g_W1b);
    cudaGetSymbolAddress((void**)&v2,  g_V2);
    cudaGetSymbolAddress((void**)&ki1, g_kidx1);
    cudaGetSymbolAddress((void**)&ci1, g_cnt1);
    cudaGetSymbolAddress((void**)&ki2, g_kidx2);
    cudaGetSymbolAddress((void**)&ci2, g_cnt2);

    cudaFuncSetAttribute(hmma_comp,
                         cudaFuncAttributeMaxDynamicSharedMemorySize, SMEMC);

    // #1: fused zgemm1 + W2T transpose + W1 cast + W1 norms (W-only overlap)
    fused_prep1<<<128 + 513 + 1024 + 128, 256>>>(x, W1, b1, W2, z1p, h1p);
    // #2: fused zgemm2 + compact(z1)
    fused_prep2<<<64 + 256, 256>>>(h1p, W2, b2, z1p, z2p, h2p);
    // #3: fused zgemm3 + compact(z2) + W3T cast
    fused_prep3<<<32 + 256 + 513, 256>>>(h2p, W3, b3, z2p, z3p);
    // #4 (profiled): layer-2  V2[b] = (W2 o m1[b]) @ W1 -> sq partials + V2
    hmma_comp<<<dim3(D2 / 128, 2, B_), 256, SMEMC>>>(
        w2t, w1b, (size_t)0, D1 - 1, ki1, ci1, D1 + 32,
        D2, sq2p, v2);
    // #5: layer-3  V3[b] = (W3 o m2[b]) @ V2[b] -> sq partials only
    hmma_comp<<<dim3(D3 / 128, 2, B_), 256, SMEMC>>>(
        w3t, v2, (size_t)D2 * D_, D2 - 1, ki2, ci2, D2 + 32,
        D3, sq3p, (__nv_bfloat16*)0);
    // #6, #7: smallest-10 per batch (all dists inline), deterministic sum
    topk_kernel<<<B_, 256>>>(z1p, z2p, z3p);
    final_reduce<<<1, 256>>>(out);
}

// round 17
// speedup vs baseline: 1.0524x; 1.0524x over previous
#include <cuda_runtime.h>
#include <cuda_bf16.h>
#include <math.h>
#include <stdint.h>

// Problem dims (fixed by setup_inputs)
#define B_   256
#define D_   256
#define D1   1024
#define D2   512
#define D3   256
#define NDIST (D1 + D2 + D3)   // 1792
#define KSEL 10

// ---------------- scratch (device globals; no cudaMalloc allowed) ----------
__device__ float g_z1[B_ * D1];
__device__ float g_h1[B_ * D1];
__device__ float g_z2[B_ * D2];
__device__ float g_h2[B_ * D2];
__device__ float g_z3[B_ * D3];
__device__ __nv_bfloat16 g_W2T[(D1 + 1) * D2];            // [1025][512], row 1024 = 0
__device__ __nv_bfloat16 g_W3T[(D2 + 1) * D3];            // [513][256],  row 512  = 0
__device__ __nv_bfloat16 g_W1b[D1 * D_];                  // [1024][256]
__device__ __nv_bfloat16 g_V2[(size_t)B_ * D2 * D_];      // [B][512][256] row-major
__device__ int g_kidx1[B_ * (D1 + 32)];
__device__ int g_cnt1[B_];
__device__ int g_kidx2[B_ * (D2 + 32)];
__device__ int g_cnt2[B_];
__device__ float g_invn1[D1];
__device__ float g_sqp2[2 * B_ * D2];                     // [ntile][b][m]
__device__ float g_sqp3[2 * B_ * D3];
__device__ float g_partial[B_];

// ---------------- PTX helpers ------------------------------------------------
__device__ __forceinline__ uint32_t smem_u32(const void* p) {
    uint32_t a;
    asm("{ .reg .u64 t; cvta.to.shared.u64 t, %1; cvt.u32.u64 %0, t; }"
        : "=r"(a) : "l"(p));
    return a;
}
__device__ __forceinline__ void cpasync16(uint32_t dst, const void* src) {
    asm volatile("cp.async.cg.shared.global [%0], [%1], 16;"
                 :: "r"(dst), "l"(src) : "memory");
}
__device__ __forceinline__ void ldm4t(uint32_t* r, uint32_t addr) {
    asm volatile("ldmatrix.sync.aligned.m8n8.x4.trans.shared.b16 {%0,%1,%2,%3}, [%4];"
                 : "=r"(r[0]), "=r"(r[1]), "=r"(r[2]), "=r"(r[3]) : "r"(addr));
}
__device__ __forceinline__ void mma16816(float* c, const uint32_t* a,
                                         uint32_t b0, uint32_t b1) {
    asm volatile(
        "mma.sync.aligned.m16n8k16.row.col.f32.bf16.bf16.f32 "
        "{%0,%1,%2,%3}, {%4,%5,%6,%7}, {%8,%9}, {%0,%1,%2,%3};"
        : "+f"(c[0]), "+f"(c[1]), "+f"(c[2]), "+f"(c[3])
        : "r"(a[0]), "r"(a[1]), "r"(a[2]), "r"(a[3]), "r"(b0), "r"(b1));
}

// ---------------- forward-pass GEMM body (device fn, callable from fused) ---
// BM=32, BN=64, BK=32; 256 threads; 2x4 per-thread microtile. (R13 version)
__device__ void zgemm_body(
    const float* __restrict__ X, const float* __restrict__ W,
    const float* __restrict__ bias, int M, int N, int K,
    float* __restrict__ Z, float* __restrict__ H,
    int bx, int by, float* Xs /*[32][34]*/, float* Ws /*[32][68]*/)
{
    int m0 = by * 32, n0 = bx * 64;
    int tid = threadIdx.x;
    int tx = tid & 15, ty = tid >> 4;
    int lrow = tid >> 3, lk = (tid & 7) * 4;

    float acc[2][4];
#pragma unroll
    for (int i = 0; i < 2; i++)
#pragma unroll
        for (int j = 0; j < 4; j++) acc[i][j] = 0.f;

    for (int k0 = 0; k0 < K; k0 += 32) {
        float4 xa = *(const float4*)(X + (size_t)(m0 + lrow) * K + k0 + lk);
        float4 w0 = *(const float4*)(W + (size_t)(n0 + lrow) * K + k0 + lk);
        float4 w1 = *(const float4*)(W + (size_t)(n0 + lrow + 32) * K + k0 + lk);
        __syncthreads();
        Xs[(lk + 0) * 34 + lrow] = xa.x; Xs[(lk + 1) * 34 + lrow] = xa.y;
        Xs[(lk + 2) * 34 + lrow] = xa.z; Xs[(lk + 3) * 34 + lrow] = xa.w;
        Ws[(lk + 0) * 68 + lrow] = w0.x; Ws[(lk + 1) * 68 + lrow] = w0.y;
        Ws[(lk + 2) * 68 + lrow] = w0.z; Ws[(lk + 3) * 68 + lrow] = w0.w;
        Ws[(lk + 0) * 68 + lrow + 32] = w1.x; Ws[(lk + 1) * 68 + lrow + 32] = w1.y;
        Ws[(lk + 2) * 68 + lrow + 32] = w1.z; Ws[(lk + 3) * 68 + lrow + 32] = w1.w;
        __syncthreads();
#pragma unroll
        for (int k = 0; k < 32; k++) {
            float a0 = Xs[k * 34 + ty * 2], a1 = Xs[k * 34 + ty * 2 + 1];
            float4 wv = *(float4*)&Ws[k * 68 + tx * 4];
            acc[0][0] += a0 * wv.x; acc[0][1] += a0 * wv.y;
            acc[0][2] += a0 * wv.z; acc[0][3] += a0 * wv.w;
            acc[1][0] += a1 * wv.x; acc[1][1] += a1 * wv.y;
            acc[1][2] += a1 * wv.z; acc[1][3] += a1 * wv.w;
        }
    }

#pragma unroll
    for (int i = 0; i < 2; i++) {
        int m = m0 + ty * 2 + i;
#pragma unroll
        for (int j = 0; j < 4; j++) {
            int n = n0 + tx * 4 + j;
            float zv = acc[i][j] + bias[n];
            size_t o = (size_t)m * N + n;
            Z[o] = zv;
            if (H) H[o] = zv > 0.f ? zv : 0.f;
        }
    }
}

__global__ __launch_bounds__(256) void zgemm32(
    const float* __restrict__ X, const float* __restrict__ W,
    const float* __restrict__ bias, int M, int N, int K,
    float* __restrict__ Z, float* __restrict__ H)
{
    __shared__ __align__(16) float Xs[32 * 34];
    __shared__ __align__(16) float Ws[32 * 68];
    zgemm_body(X, W, bias, M, N, K, Z, H, blockIdx.x, blockIdx.y, Xs, Ws);
}

// ---------------- deterministic per-batch active-k compaction (device fn) --
template <int KN>
__device__ __forceinline__ void compact_body(
    const float* __restrict__ z, int* __restrict__ kidx, int* __restrict__ cnt,
    int b, int t, int* sh /*[256]*/)
{
    const int E = KN / 256;
    const int kpitch = KN + 32;
    int flag[E];
    int c = 0;
#pragma unroll
    for (int e = 0; e < E; e++) {
        flag[e] = (z[(size_t)b * KN + t * E + e] > 0.f) ? 1 : 0;
        c += flag[e];
    }
    sh[t] = c;
    __syncthreads();
    for (int s = 1; s < 256; s <<= 1) {
        int x = (t >= s) ? sh[t - s] : 0;
        __syncthreads();
        sh[t] += x;
        __syncthreads();
    }
    int pos = sh[t] - c;
#pragma unroll
    for (int e = 0; e < E; e++)
        if (flag[e]) kidx[(size_t)b * kpitch + pos++] = t * E + e;
    int total = sh[255];
    int padded = (total + 31) & ~31;
    int ip = total + t;
    if (ip < padded) kidx[(size_t)b * kpitch + ip] = KN;  // -> zero row of A^T
    if (t == 0) cnt[b] = total;
}

// fused #2: zgemm2 (64 blks) + compact(z1) + W2T tile-transpose + pad row
//           + W1 cast + W1 row inv-norms
// grid = 64 + 256 + 512 + 1 + 1024 + 128 = 1985
__global__ __launch_bounds__(256) void fused_prep2(
    const float* __restrict__ h1, const float* __restrict__ W2,
    const float* __restrict__ b2,
    const float* __restrict__ z1, const float* __restrict__ W1,
    float* __restrict__ z2, float* __restrict__ h2)
{
    __shared__ __align__(16) float smem[32 * 68 + 32 * 34];
    int blk = blockIdx.x, t = threadIdx.x;
    if (blk < 64) {
        // z2 = h1 @ W2^T + b2   (grid 8x8: bx = blk&7, by = blk>>3)
        zgemm_body(h1, W2, b2, B_, D2, D1, z2, h2,
                   blk & 7, blk >> 3, smem, smem + 32 * 34);
    } else if (blk < 64 + 256) {
        compact_body<D1>(z1, g_kidx1, g_cnt1, blk - 64, t, (int*)smem);
    } else if (blk < 64 + 256 + 512) {
        // transpose one 32(m) x 32(k) tile of W2 [512][1024] -> W2T [1025][512]
        float* tile = smem;   // [32][33]
        int bi = blk - 64 - 256;
        int k0 = (bi & 31) * 32, m0 = (bi >> 5) * 32;
        int r = t >> 3, c4 = (t & 7) * 4;
        float4 v = *(const float4*)(W2 + (size_t)(m0 + r) * D1 + k0 + c4);
        tile[r * 33 + c4 + 0] = v.x; tile[r * 33 + c4 + 1] = v.y;
        tile[r * 33 + c4 + 2] = v.z; tile[r * 33 + c4 + 3] = v.w;
        __syncthreads();
        __nv_bfloat16 o[4];
#pragma unroll
        for (int i = 0; i < 4; i++) o[i] = __float2bfloat16(tile[(c4 + i) * 33 + r]);
        *(uint2*)&g_W2T[(size_t)(k0 + r) * D2 + m0 + c4] = *(uint2*)o;
    } else if (blk < 64 + 256 + 512 + 1) {
        if (t < 128)
            ((uint2*)&g_W2T[(size_t)D1 * D2])[t] = make_uint2(0u, 0u);
    } else if (blk < 64 + 256 + 513 + 1024) {
        int i = (blk - 64 - 256 - 513) * 256 + t;
        g_W1b[i] = __float2bfloat16(W1[i]);
    } else {
        int warp = (blk - 64 - 256 - 513 - 1024) * 8 + (t >> 5);
        int lane = t & 31;
        const float4* vp = (const float4*)(W1 + (size_t)warp * D_);
        float4 v0 = vp[lane * 2], v1 = vp[lane * 2 + 1];
        float s = v0.x * v0.x + v0.y * v0.y + v0.z * v0.z + v0.w * v0.w
                + v1.x * v1.x + v1.y * v1.y + v1.z * v1.z + v1.w * v1.w;
#pragma unroll
        for (int o = 16; o; o >>= 1) s += __shfl_xor_sync(0xffffffffu, s, o);
        if (lane == 0) g_invn1[warp] = rsqrtf(s);
    }
}

// fused #3: zgemm3 (32 blks) + compact(z2) + W3T cast.  grid = 32 + 256 + 513
__global__ __launch_bounds__(256) void fused_prep3(
    const float* __restrict__ h2, const float* __restrict__ W3,
    const float* __restrict__ b3,
    const float* __restrict__ z2, float* __restrict__ z3)
{
    __shared__ __align__(16) float smem[32 * 68 + 32 * 34];
    int blk = blockIdx.x, t = threadIdx.x;
    if (blk < 32) {
        // z3 = h2 @ W3^T + b3   (grid 4x8: bx = blk&3, by = blk>>2)
        zgemm_body(h2, W3, b3, B_, D3, D2, z3, (float*)0,
                   blk & 3, blk >> 2, smem, smem + 32 * 34);
    } else if (blk < 32 + 256) {
        compact_body<D2>(z2, g_kidx2, g_cnt2, blk - 32, t, (int*)smem);
    } else {
        int i = (blk - 32 - 256) * 256 + t;
        if (i < (D2 + 1) * D3) {
            int k = i >> 8, m = i & 255;
            g_W3T[i] = (k < D2) ? __float2bfloat16(W3[(size_t)m * D2 + k])
                                : __float2bfloat16(0.f);
        }
    }
}

// ---------------- HMMA k-compacted batched GEMM (128x128 tile) --------------
// grid (Mtot/128, 2 ntiles, B_); 256 threads; 2 CTAs/SM.
// 4-stage cp.async ring, depth-3 prefetch, B-fragment double buffering.
// (R10/R13 configuration. Mainloop untouched; V writeback now predicated on
//  zmask>0 — inactive rows are never gathered by layer 3 except through the
//  zero A-row pad, so skipping them is bit-exact.)
#define APITCH 272               // 32k x 128m bf16 rows padded to 272B
#define BPITCH 272               // 32k x 128n bf16 rows padded to 272B
#define ASTG   (32 * APITCH)     // 8704
#define BSTG   (32 * BPITCH)     // 8704
#define STGC   (ASTG + BSTG)     // 17408
#define NSTG   4
#define SQOFF  (NSTG * STGC)     // 69632
#define SMEMC  (SQOFF + 1024)

__global__ __launch_bounds__(256, 2) void hmma_comp(
    const __nv_bfloat16* __restrict__ AT, const __nv_bfloat16* __restrict__ Bk,
    size_t bstrideB, int bclamp,
    const int* __restrict__ kidx, const int* __restrict__ cnt, int kpitch,
    int Mtot, float* __restrict__ sqout,
    __nv_bfloat16* __restrict__ Vout, const float* __restrict__ zmask)
{
    extern __shared__ __align__(16) char smem[];
    const uint32_t sb = smem_u32(smem);
    const int tid = threadIdx.x, wid = tid >> 5, lane = tid & 31;
    const int warpM = wid >> 1, warpN = wid & 1;   // 4 x 2, warp tile 32x64
    const int m0 = blockIdx.x * 128, n0 = blockIdx.y * 128;
    const int b = blockIdx.z;

    const __nv_bfloat16* Bb = Bk + (size_t)b * bstrideB;
    const int* kp = kidx + (size_t)b * kpitch;
    const int nch = (cnt[b] + 31) >> 5;

    float c[2][8][4];
#pragma unroll
    for (int i = 0; i < 2; i++)
#pragma unroll
        for (int j = 0; j < 8; j++)
#pragma unroll
            for (int r = 0; r < 4; r++) c[i][j][r] = 0.f;

    const int gr = tid >> 3;          // 0..31: gathered row within chunk
    const int sg = tid & 7;           // 8 threads per row; 2x16B segs each

    auto load_stage = [&](int s, int cc) {
        if (cc < nch) {
            uint32_t st = sb + s * STGC;
            int k = __ldg(kp + cc * 32 + gr);
            const __nv_bfloat16* asrc = AT + (size_t)k * Mtot + m0 + sg * 16;
            cpasync16(st + gr * APITCH + sg * 32, asrc);
            cpasync16(st + gr * APITCH + sg * 32 + 16, asrc + 8);
            int kb = min(k, bclamp);
            const __nv_bfloat16* bsrc = Bb + (size_t)kb * 256 + n0 + sg * 16;
            cpasync16(st + ASTG + gr * BPITCH + sg * 32, bsrc);
            cpasync16(st + ASTG + gr * BPITCH + sg * 32 + 16, bsrc + 8);
        }
        asm volatile("cp.async.commit_group;" ::: "memory");
    };

    if (nch > 0) {
        load_stage(0, 0);
        load_stage(1, 1);
        load_stage(2, 2);

        const int kr = (lane & 7) + ((lane >> 4) << 3);  // k-row within 16-blk
        const int ch8 = ((lane >> 3) & 1) << 3;          // +8 col for odd octet

        for (int cidx = 0; cidx < nch; cidx++) {
            int cur = cidx & (NSTG - 1);
            asm volatile("cp.async.wait_group 2;" ::: "memory");
            __syncthreads();
            load_stage((cidx + 3) & (NSTG - 1), cidx + 3);

            uint32_t aBase = sb + cur * STGC;
            uint32_t bBase = aBase + ASTG;
#pragma unroll
            for (int ks = 0; ks < 2; ks++) {
                uint32_t arow = aBase + (uint32_t)(ks * 16 + kr) * APITCH;
                uint32_t brow = bBase + (uint32_t)(ks * 16 + kr) * BPITCH;
                uint32_t a0[4], a1[4], bcur[4], bnxt[4];
                ldm4t(a0, arow + (uint32_t)(warpM * 32 + ch8) * 2);
                ldm4t(a1, arow + (uint32_t)(warpM * 32 + 16 + ch8) * 2);
                ldm4t(bcur, brow + (uint32_t)(warpN * 64 + ch8) * 2);
#pragma unroll
                for (int gi = 0; gi < 4; gi++) {
                    if (gi < 3)
                        ldm4t(bnxt, brow + (uint32_t)(warpN * 64 + (gi + 1) * 16 + ch8) * 2);
                    mma16816(c[0][gi * 2],     a0, bcur[0], bcur[2]);
                    mma16816(c[0][gi * 2 + 1], a0, bcur[1], bcur[3]);
                    mma16816(c[1][gi * 2],     a1, bcur[0], bcur[2]);
                    mma16816(c[1][gi * 2 + 1], a1, bcur[1], bcur[3]);
                    bcur[0] = bnxt[0]; bcur[1] = bnxt[1];
                    bcur[2] = bnxt[2]; bcur[3] = bnxt[3];
                }
            }
        }
        asm volatile("cp.async.wait_group 0;" ::: "memory");
        __syncthreads();
    }

    // ---- per-row partial sum-of-squares (deterministic order) ----
    float* sqsm = (float*)(smem + SQOFF);   // [2 warpN][128 rows]
    {
        float rs[2][2] = {{0.f, 0.f}, {0.f, 0.f}};
#pragma unroll
        for (int mi = 0; mi < 2; mi++)
#pragma unroll
            for (int nj = 0; nj < 8; nj++)
#pragma unroll
                for (int r = 0; r < 4; r++) {
                    float v = c[mi][nj][r];
                    rs[mi][r >> 1] += v * v;
                }
#pragma unroll
        for (int mi = 0; mi < 2; mi++)
#pragma unroll
            for (int h = 0; h < 2; h++) {
                float v = rs[mi][h];
                v += __shfl_xor_sync(0xffffffffu, v, 1);
                v += __shfl_xor_sync(0xffffffffu, v, 2);
                rs[mi][h] = v;
            }
        if ((lane & 3) == 0) {
#pragma unroll
            for (int mi = 0; mi < 2; mi++)
#pragma unroll
                for (int h = 0; h < 2; h++)
                    sqsm[warpN * 128 + warpM * 32 + mi * 16 + h * 8 + (lane >> 2)]
                        = rs[mi][h];
        }
    }
    __syncthreads();
    if (tid < 128) {
        float s = sqsm[tid] + sqsm[128 + tid];
        sqout[((size_t)blockIdx.y * B_ + b) * Mtot + m0 + tid] = s;
    }

    // ---- V writeback (row-major C, layer 2 only; active rows only) ----
    if (Vout) {
        __nv_bfloat16* Vb = Vout + (size_t)b * Mtot * 256;
        const float* zb = zmask + (size_t)b * Mtot;
#pragma unroll
        for (int mi = 0; mi < 2; mi++)
#pragma unroll
            for (int rp = 0; rp < 2; rp++) {
                int row = m0 + warpM * 32 + mi * 16 + rp * 8 + (lane >> 2);
                bool act = zb[row] > 0.f;
                if (act) {
#pragma unroll
                    for (int nj = 0; nj < 8; nj++) {
                        int col = n0 + warpN * 64 + nj * 8 + (lane & 3) * 2;
                        __nv_bfloat162 p;
                        p.x = __float2bfloat16(c[mi][nj][rp * 2]);
                        p.y = __float2bfloat16(c[mi][nj][rp * 2 + 1]);
                        *(__nv_bfloat162*)(Vb + (size_t)row * 256 + col) = p;
                    }
                }
            }
    }
}

// ---------------- per-batch smallest-k sum (warp-shuffle argmin) ------------
__global__ void topk_kernel(const float* __restrict__ z1,
                            const float* __restrict__ z2,
                            const float* __restrict__ z3)
{
    __shared__ float s[NDIST];
    __shared__ float wv[8];
    __shared__ int   wi[8];
    int b = blockIdx.x, t = threadIdx.x;
    int wid = t >> 5, lane = t & 31;

    for (int i = t; i < D1; i += 256)
        s[i] = fabsf(z1[(size_t)b * D1 + i]) * g_invn1[i];
    for (int i = t; i < D2; i += 256) {
        float sq = g_sqp2[(size_t)b * D2 + i] + g_sqp2[(size_t)(B_ + b) * D2 + i];
        s[D1 + i] = fabsf(z2[(size_t)b * D2 + i]) * rsqrtf(sq);
    }
    if (t < D3) {
        float sq = g_sqp3[(size_t)b * D3 + t] + g_sqp3[(size_t)(B_ + b) * D3 + t];
        s[D1 + D2 + t] = fabsf(z3[(size_t)b * D3 + t]) * rsqrtf(sq);
    }
    __syncthreads();

    float tot = 0.f;
    for (int it = 0; it < KSEL; it++) {
        float best = 3.402823466e38f; int bi = NDIST;
        for (int i = t; i < NDIST; i += 256) {
            float v = s[i];
            if (v < best) { best = v; bi = i; }
        }
#pragma unroll
        for (int off = 16; off; off >>= 1) {
            float ov = __shfl_down_sync(0xffffffffu, best, off);
            int   oi = __shfl_down_sync(0xffffffffu, bi,   off);
            if (ov < best || (ov == best && oi < bi)) { best = ov; bi = oi; }
        }
        if (lane == 0) { wv[wid] = best; wi[wid] = bi; }
        __syncthreads();
        if (wid == 0) {
            float fb = (lane < 8) ? wv[lane] : 3.402823466e38f;
            int   fi = (lane < 8) ? wi[lane] : NDIST;
#pragma unroll
            for (int off = 4; off; off >>= 1) {
                float ov = __shfl_down_sync(0xffffffffu, fb, off);
                int   oi = __shfl_down_sync(0xffffffffu, fi, off);
                if (ov < fb || (ov == fb && oi < fi)) { fb = ov; fi = oi; }
            }
            if (lane == 0) { tot += fb; s[fi] = 3.402823466e38f; }
        }
        __syncthreads();
    }
    if (t == 0) g_partial[b] = tot;
}

__global__ void final_reduce(float* __restrict__ out)
{
    __shared__ float sh[256];
    int t = threadIdx.x;
    sh[t] = g_partial[t];
    __syncthreads();
    for (int st = 128; st > 0; st >>= 1) {
        if (t < st) sh[t] += sh[t + st];
        __syncthreads();
    }
    if (t == 0) out[0] = sh[0];
}

// ---------------- launch -----------------------------------------------------
extern "C" void kernel_launch(void* const* d_in, const int* in_sizes, int n_in,
                              void* d_out, int out_size)
{
    const float* x  = (const float*)d_in[0];
    const float* W1 = (const float*)d_in[1];
    const float* b1 = (const float*)d_in[2];
    const float* W2 = (const float*)d_in[3];
    const float* b2 = (const float*)d_in[4];
    const float* W3 = (const float*)d_in[5];
    const float* b3 = (const float*)d_in[6];
    float* out = (float*)d_out;

    float *z1p, *h1p, *z2p, *h2p, *z3p, *sq2p, *sq3p;
    __nv_bfloat16 *w2t, *w3t, *w1b, *v2;
    int *ki1, *ci1, *ki2, *ci2;
    cudaGetSymbolAddress((void**)&z1p, g_z1);
    cudaGetSymbolAddress((void**)&h1p, g_h1);
    cudaGetSymbolAddress((void**)&z2p, g_z2);
    cudaGetSymbolAddress((void**)&h2p, g_h2);
    cudaGetSymbolAddress((void**)&z3p, g_z3);
    cudaGetSymbolAddress((void**)&sq2p, g_sqp2);
    cudaGetSymbolAddress((void**)&sq3p, g_sqp3);
    cudaGetSymbolAddress((void**)&w2t, g_W2T);
    cudaGetSymbolAddress((void**)&w3t, g_W3T);
    cudaGetSymbolAddress((void**)&w1b, g_W1b);
    cudaGetSymbolAddress((void**)&v2,  g_V2);
    cudaGetSymbolAddress((void**)&ki1, g_kidx1);
    cudaGetSymbolAddress((void**)&ci1, g_cnt1);
    cudaGetSymbolAddress((void**)&ki2, g_kidx2);
    cudaGetSymbolAddress((void**)&ci2, g_cnt2);

    cudaFuncSetAttribute(hmma_comp,
                         cudaFuncAttributeMaxDynamicSharedMemorySize, SMEMC);

    // #1: layer-1 forward  z1 = x @ W1^T + b1
    zgemm32<<<dim3(D1 / 64, B_ / 32), 256>>>(x, W1, b1, B_, D1, D_, z1p, h1p);
    // #2: fused zgemm2 + compact(z1) + W2T transpose + W1 cast + W1 norms
    fused_prep2<<<64 + 256 + 513 + 1024 + 128, 256>>>(h1p, W2, b2, z1p, W1,
                                                      z2p, h2p);
    // #3: fused zgemm3 + compact(z2) + W3T cast
    fused_prep3<<<32 + 256 + 513, 256>>>(h2p, W3, b3, z2p, z3p);
    // #4 (profiled): layer-2  V2[b] = (W2 o m1[b]) @ W1 -> sq partials + V2
    hmma_comp<<<dim3(D2 / 128, 2, B_), 256, SMEMC>>>(
        w2t, w1b, (size_t)0, D1 - 1, ki1, ci1, D1 + 32,
        D2, sq2p, v2, z2p);
    // #5: layer-3  V3[b] = (W3 o m2[b]) @ V2[b] -> sq partials only
    hmma_comp<<<dim3(D3 / 128, 2, B_), 256, SMEMC>>>(
        w3t, v2, (size_t)D2 * D_, D2 - 1, ki2, ci2, D2 + 32,
        D3, sq3p, (__nv_bfloat16*)0, (const float*)0);
    // #6, #7: smallest-10 per batch (all dists inline), deterministic sum
    topk_kernel<<<B_, 256>>>(z1p, z2p, z3p);
    final_reduce<<<1, 256>>>(out);
}